// round 13
// baseline (speedup 1.0000x reference)
#include <cuda_runtime.h>
#include <cuda_bf16.h>
#include <math.h>
#include <stdint.h>

#define NB 64
#define LG 1024
#define NN (NB*LG)
#define KK 16
#define INF_ 128
#define OUTF 128
#define SS 4
#define FLR 64
#define FEAT 256

// Scratch (device globals: allocation is forbidden)
__device__ float g_s[NN * SS];
__device__ float g_h[NN * FLR];
__device__ float g_agg[NN * 2 * FLR];
__device__ uint32_t g_Wbhi[128 * 128];    // W_out^T bf16-hi [n][kw]
__device__ uint32_t g_Wblo[128 * 128];    // W_out^T bf16-lo
__device__ uint32_t g_Whhi[64 * 64];      // W_h^T bf16-hi [n][kw]
__device__ uint32_t g_Whlo[64 * 64];      // W_h^T bf16-lo

// ---------------------------------------------------------------------------
// helpers
// ---------------------------------------------------------------------------
__device__ __forceinline__ uint32_t s2u(const void* p) {
    uint32_t a;
    asm("{ .reg .u64 t; cvta.to.shared.u64 t, %1; cvt.u32.u64 %0, t; }" : "=r"(a) : "l"(p));
    return a;
}
__device__ __forceinline__ uint32_t pk_hi(float a, float b) {
    uint32_t p;
    asm("cvt.rn.bf16x2.f32 %0, %1, %2;" : "=r"(p) : "f"(b), "f"(a));
    return p;   // low16 = bf16(a), high16 = bf16(b)
}
__device__ __forceinline__ uint32_t pk_lo_from(uint32_t ph, float a, float b) {
    float ha = __uint_as_float(ph << 16);
    float hb = __uint_as_float(ph & 0xFFFF0000u);
    return pk_hi(a - ha, b - hb);
}
__device__ __forceinline__ void sts128(uint32_t addr, uint32_t a, uint32_t b, uint32_t c, uint32_t d) {
    asm volatile("st.shared.v4.b32 [%0], {%1,%2,%3,%4};" :: "r"(addr), "r"(a), "r"(b), "r"(c), "r"(d) : "memory");
}
__device__ __forceinline__ void ldsm4(uint32_t* r, uint32_t addr) {
    asm volatile("ldmatrix.sync.aligned.m8n8.x4.shared.b16 {%0,%1,%2,%3}, [%4];"
        : "=r"(r[0]), "=r"(r[1]), "=r"(r[2]), "=r"(r[3]) : "r"(addr));
}
__device__ __forceinline__ void mma16816(float* c, const uint32_t* a, uint32_t b0, uint32_t b1) {
    asm volatile("mma.sync.aligned.m16n8k16.row.col.f32.bf16.bf16.f32 "
        "{%0,%1,%2,%3}, {%4,%5,%6,%7}, {%8,%9}, {%0,%1,%2,%3};"
        : "+f"(c[0]), "+f"(c[1]), "+f"(c[2]), "+f"(c[3])
        : "r"(a[0]), "r"(a[1]), "r"(a[2]), "r"(a[3]), "r"(b0), "r"(b1));
}

// ---------------------------------------------------------------------------
// Kernel 0: W_out and W_h -> bf16 hi/lo splits, B layout [n][k]
// ---------------------------------------------------------------------------
__global__ __launch_bounds__(256) void k0_convW(
    const float* __restrict__ Wout, const float* __restrict__ Wh)
{
    int idx = blockIdx.x * 256 + threadIdx.x;   // 0..20479
    if (idx < 16384) {
        int n = idx >> 7, kw = idx & 127;
        float w0 = Wout[(size_t)(2 * kw) * OUTF + n];
        float w1 = Wout[(size_t)(2 * kw + 1) * OUTF + n];
        uint32_t ph = pk_hi(w0, w1);
        g_Wbhi[idx] = ph;
        g_Wblo[idx] = pk_lo_from(ph, w0, w1);
    } else {
        int i2 = idx - 16384;                   // 0..4095
        int n = i2 >> 6, kw = i2 & 63;
        float w0 = Wh[(size_t)(2 * kw) * FLR + n];
        float w1 = Wh[(size_t)(2 * kw + 1) * FLR + n];
        uint32_t ph = pk_hi(w0, w1);
        g_Whhi[i2] = ph;
        g_Whlo[i2] = pk_lo_from(ph, w0, w1);
    }
}

// ---------------------------------------------------------------------------
// Kernel 1s: s = x@W_s + b_s (fp32 exact — keeps kNN selection bit-identical).
// Warp per row, 4 rows per warp.
// ---------------------------------------------------------------------------
__global__ __launch_bounds__(256) void k1s(
    const float* __restrict__ x, const float* __restrict__ Ws,
    const float* __restrict__ bs)
{
    int tid = threadIdx.x, warp = tid >> 5, lane = tid & 31;
    float4 wk0 = ((const float4*)Ws)[lane * 4 + 0];
    float4 wk1 = ((const float4*)Ws)[lane * 4 + 1];
    float4 wk2 = ((const float4*)Ws)[lane * 4 + 2];
    float4 wk3 = ((const float4*)Ws)[lane * 4 + 3];
    float4 bsv = *(const float4*)bs;

    int row0 = (blockIdx.x * 8 + warp) * 4;
    #pragma unroll
    for (int r = 0; r < 4; r++) {
        int row = row0 + r;
        float4 xv = ((const float4*)(x + (size_t)row * INF_))[lane];
        float4 a;
        a.x = xv.x * wk0.x; a.y = xv.x * wk0.y; a.z = xv.x * wk0.z; a.w = xv.x * wk0.w;
        a.x = fmaf(xv.y, wk1.x, a.x); a.y = fmaf(xv.y, wk1.y, a.y);
        a.z = fmaf(xv.y, wk1.z, a.z); a.w = fmaf(xv.y, wk1.w, a.w);
        a.x = fmaf(xv.z, wk2.x, a.x); a.y = fmaf(xv.z, wk2.y, a.y);
        a.z = fmaf(xv.z, wk2.z, a.z); a.w = fmaf(xv.z, wk2.w, a.w);
        a.x = fmaf(xv.w, wk3.x, a.x); a.y = fmaf(xv.w, wk3.y, a.y);
        a.z = fmaf(xv.w, wk3.z, a.z); a.w = fmaf(xv.w, wk3.w, a.w);
        #pragma unroll
        for (int off = 16; off; off >>= 1) {
            a.x += __shfl_xor_sync(0xffffffffu, a.x, off);
            a.y += __shfl_xor_sync(0xffffffffu, a.y, off);
            a.z += __shfl_xor_sync(0xffffffffu, a.z, off);
            a.w += __shfl_xor_sync(0xffffffffu, a.w, off);
        }
        if (lane == 0) {
            float4 o;
            o.x = a.x + bsv.x; o.y = a.y + bsv.y;
            o.z = a.z + bsv.z; o.w = a.w + bsv.w;
            ((float4*)g_s)[row] = o;
        }
    }
}

// ---------------------------------------------------------------------------
// Kernel 1h: h = x@W_h + b_h via HMMA bf16x3 (clones k3's proven skeleton,
// N=64). Tile: 128 rows x 64 cols, K=128. 8 warps: 4 M-groups x 2 N-groups.
// ---------------------------------------------------------------------------
#define H_AROW 272
#define H_BROW 272
#define H_AHI  0
#define H_ALO  34816
#define H_BHI  69632
#define H_BLO  87040
#define H_SMEM 104448

__global__ __launch_bounds__(256, 1) void k1h(
    const float* __restrict__ x, const float* __restrict__ bh)
{
    extern __shared__ __align__(16) char smem[];
    uint32_t sb = s2u(smem);
    int tid = threadIdx.x, warp = tid >> 5, lane = tid & 31;
    int wm = warp >> 1, wn = warp & 1;
    int r0 = blockIdx.x * 128;

    // stage B (W_h^T hi/lo)
    #pragma unroll
    for (int i = tid; i < 1024; i += 256) {
        uint4 vh = ((const uint4*)g_Whhi)[i];
        uint4 vl = ((const uint4*)g_Whlo)[i];
        int n = i >> 4, c = i & 15;
        uint32_t off = (uint32_t)n * H_BROW + (uint32_t)c * 16;
        sts128(sb + H_BHI + off, vh.x, vh.y, vh.z, vh.w);
        sts128(sb + H_BLO + off, vl.x, vl.y, vl.z, vl.w);
    }

    // convert A: x tile -> hi/lo bf16 smem (single global read)
    #pragma unroll
    for (int i = tid; i < 2048; i += 256) {
        int row = i >> 4, kk = (i & 15) * 8;
        const float* gp = x + (size_t)(r0 + row) * 128 + kk;
        float4 v0 = ((const float4*)gp)[0];
        float4 v1 = ((const float4*)gp)[1];
        uint32_t h0 = pk_hi(v0.x, v0.y), h1 = pk_hi(v0.z, v0.w);
        uint32_t h2 = pk_hi(v1.x, v1.y), h3 = pk_hi(v1.z, v1.w);
        uint32_t off = (uint32_t)row * H_AROW + (uint32_t)kk * 2;
        sts128(sb + H_AHI + off, h0, h1, h2, h3);
        sts128(sb + H_ALO + off,
               pk_lo_from(h0, v0.x, v0.y), pk_lo_from(h1, v0.z, v0.w),
               pk_lo_from(h2, v1.x, v1.y), pk_lo_from(h3, v1.z, v1.w));
    }
    __syncthreads();

    uint32_t aoff[2];
    #pragma unroll
    for (int mi = 0; mi < 2; mi++)
        aoff[mi] = (uint32_t)(wm * 32 + mi * 16 + (lane & 15)) * H_AROW
                 + (uint32_t)((lane >> 4) * 16);
    uint32_t boff = (uint32_t)(wn * 32 + (lane & 7) + ((lane >> 4) << 3)) * H_BROW
                  + (uint32_t)(((lane >> 3) & 1) * 16);

    float c[2][4][4];
    #pragma unroll
    for (int mi = 0; mi < 2; mi++)
        #pragma unroll
        for (int f = 0; f < 4; f++)
            #pragma unroll
            for (int q = 0; q < 4; q++) c[mi][f][q] = 0.f;

    #pragma unroll
    for (int ks = 0; ks < 8; ks++) {
        uint32_t kb = (uint32_t)ks * 32;
        uint32_t ah[2][4], al[2][4], bhf[2][4], blf[2][4];
        ldsm4(ah[0], sb + H_AHI + aoff[0] + kb);
        ldsm4(ah[1], sb + H_AHI + aoff[1] + kb);
        ldsm4(al[0], sb + H_ALO + aoff[0] + kb);
        ldsm4(al[1], sb + H_ALO + aoff[1] + kb);
        #pragma unroll
        for (int j2 = 0; j2 < 2; j2++) {
            uint32_t ro = boff + (uint32_t)j2 * (16 * H_BROW) + kb;
            ldsm4(bhf[j2], sb + H_BHI + ro);
            ldsm4(blf[j2], sb + H_BLO + ro);
        }
        #pragma unroll
        for (int mi = 0; mi < 2; mi++)
            #pragma unroll
            for (int f = 0; f < 4; f++) {
                uint32_t b0 = bhf[f >> 1][(f & 1) * 2], b1 = bhf[f >> 1][(f & 1) * 2 + 1];
                uint32_t l0 = blf[f >> 1][(f & 1) * 2], l1 = blf[f >> 1][(f & 1) * 2 + 1];
                mma16816(c[mi][f], ah[mi], b0, b1);
                mma16816(c[mi][f], ah[mi], l0, l1);
                mma16816(c[mi][f], al[mi], b0, b1);
            }
    }

    // epilogue: + b_h, no relu
    #pragma unroll
    for (int mi = 0; mi < 2; mi++) {
        int row = r0 + wm * 32 + mi * 16 + (lane >> 2);
        #pragma unroll
        for (int f = 0; f < 4; f++) {
            int col = wn * 32 + f * 8 + (lane & 3) * 2;
            float2 bv = *(const float2*)(bh + col);
            float2 v0, v1;
            v0.x = c[mi][f][0] + bv.x; v0.y = c[mi][f][1] + bv.y;
            v1.x = c[mi][f][2] + bv.x; v1.y = c[mi][f][3] + bv.y;
            *(float2*)(g_h + (size_t)row * FLR + col)       = v0;
            *(float2*)(g_h + (size_t)(row + 8) * FLR + col) = v1;
        }
    }
}

// ---------------------------------------------------------------------------
// Kernel 2: per-graph kNN + aggregate. Tournament selection:
// per-lane 8 cached group-minima (groups of 4); per pass only the winning
// lane/group recomputes. Distinct-value semantics identical to R11 code.
// ---------------------------------------------------------------------------
__global__ __launch_bounds__(256) void k2_knn_agg()
{
    __shared__ float4 s_sh[LG];
    __shared__ float  sq_sh[LG];
    __shared__ int    sel_j[8][KK];
    __shared__ float  sel_d[8][KK];

    int g  = blockIdx.x >> 7;
    int nb = blockIdx.x & 127;
    int tid = threadIdx.x, warp = tid >> 5, lane = tid & 31;
    int gbase = g * LG;

    const float4* sg = (const float4*)(g_s + (size_t)gbase * SS);
    for (int i = tid; i < LG; i += 256) {
        float4 v = sg[i];
        s_sh[i] = v;
        sq_sh[i] = v.x*v.x + v.y*v.y + v.z*v.z + v.w*v.w;
    }
    __syncthreads();

    int li = nb * 8 + warp;
    float4 si = s_sh[li];
    float sqi = sq_sh[li];

    unsigned u[32];
    #pragma unroll
    for (int c = 0; c < 32; c++) {
        int j = (c << 5) | lane;
        float4 sj = s_sh[j];
        float dot = si.x*sj.x + si.y*sj.y + si.z*sj.z + si.w*sj.w;
        float v = fmaxf(sqi + sq_sh[j] - 2.f * dot, 0.f);
        u[c] = __float_as_uint(v);
    }

    // group minima (8 groups of 4) + lane min
    unsigned gm[8];
    #pragma unroll
    for (int gg = 0; gg < 8; gg++)
        gm[gg] = min(min(u[4*gg], u[4*gg+1]), min(u[4*gg+2], u[4*gg+3]));
    unsigned lmin = gm[0];
    #pragma unroll
    for (int gg = 1; gg < 8; gg++) lmin = min(lmin, gm[gg]);

    unsigned wmv = 0;
    #pragma unroll 1
    for (int t = 0; t < KK; t++) {
        unsigned wm2 = lmin;
        #pragma unroll
        for (int off = 16; off; off >>= 1)
            wm2 = min(wm2, __shfl_xor_sync(0xffffffffu, wm2, off));
        wmv = wm2;
        if (lmin == wm2) {
            unsigned b = wm2 + 1u;
            #pragma unroll
            for (int gg = 0; gg < 8; gg++) {
                if (gm[gg] == wm2) {
                    unsigned m0 = min(u[4*gg]   - b, u[4*gg+1] - b);
                    unsigned m1 = min(u[4*gg+2] - b, u[4*gg+3] - b);
                    unsigned mm = min(m0, m1);
                    gm[gg] = (mm & 0x80000000u) ? 0xFFFFFFFFu : (b + mm);
                }
            }
            lmin = gm[0];
            #pragma unroll
            for (int gg = 1; gg < 8; gg++) lmin = min(lmin, gm[gg]);
        }
    }
    int TI = (int)wmv;   // 16th smallest (distinct) value bits

    // compact indices with u <= T (ascending j, capped at 16)
    int cbase = 0;
    unsigned lmask = (1u << lane) - 1u;
    #pragma unroll
    for (int c = 0; c < 32; c++) {
        bool p = ((int)u[c] <= TI);
        unsigned m = __ballot_sync(0xffffffffu, p);
        if (p) {
            int pos = cbase + __popc(m & lmask);
            if (pos < KK) {
                sel_j[warp][pos] = (c << 5) | lane;
                sel_d[warp][pos] = __uint_as_float(u[c]);
            }
        }
        cbase += __popc(m);
    }
    __syncwarp();

    float m0 = 0.f, m1 = 0.f, x0 = -3.4e38f, x1 = -3.4e38f;
    #pragma unroll 4
    for (int t = 0; t < KK; t++) {
        int   j  = sel_j[warp][t];
        float wt = __expf(-10.f * sel_d[warp][t]);
        const float* hp = g_h + (size_t)(gbase + j) * FLR;
        float v0 = hp[lane]      * wt;
        float v1 = hp[lane + 32] * wt;
        m0 += v0; m1 += v1;
        x0 = fmaxf(x0, v0); x1 = fmaxf(x1, v1);
    }
    float* ap = g_agg + (size_t)(gbase + li) * (2 * FLR);
    ap[lane]      = m0 * (1.f / 16.f);
    ap[lane + 32] = m1 * (1.f / 16.f);
    ap[64 + lane] = x0;
    ap[96 + lane] = x1;
}

// ---------------------------------------------------------------------------
// Kernel 3 (unchanged from R11): HMMA bf16x3 GEMM for the output layer.
// ---------------------------------------------------------------------------
#define K3_AROW 272
#define K3_BROW 528
#define A_HI    0
#define A_LO    34816
#define B_HI    69632
#define B_LO    137216
#define K3_SMEM 204800

__global__ __launch_bounds__(256, 1) void k3_mma(
    const float* __restrict__ x,
    const float* __restrict__ bout,
    float* __restrict__ out)
{
    extern __shared__ __align__(16) char smem[];
    uint32_t sb = s2u(smem);
    int tid = threadIdx.x, warp = tid >> 5, lane = tid & 31;
    int wm = warp >> 1, wn = warp & 1;

    #pragma unroll 4
    for (int i = tid; i < 4096; i += 256) {
        uint4 vh = ((const uint4*)g_Wbhi)[i];
        uint4 vl = ((const uint4*)g_Wblo)[i];
        int n = i >> 5, c = i & 31;
        uint32_t off = (uint32_t)n * K3_BROW + (uint32_t)c * 16;
        sts128(sb + B_HI + off, vh.x, vh.y, vh.z, vh.w);
        sts128(sb + B_LO + off, vl.x, vl.y, vl.z, vl.w);
    }

    float2 bias[8];
    #pragma unroll
    for (int f = 0; f < 8; f++)
        bias[f] = *(const float2*)(bout + wn * 64 + f * 8 + (lane & 3) * 2);

    uint32_t aoff[2];
    #pragma unroll
    for (int mi = 0; mi < 2; mi++)
        aoff[mi] = (uint32_t)(wm * 32 + mi * 16 + (lane & 15)) * K3_AROW
                 + (uint32_t)((lane >> 4) * 16);
    uint32_t boff = (uint32_t)(wn * 64 + (lane & 7) + ((lane >> 4) << 3)) * K3_BROW
                  + (uint32_t)(((lane >> 3) & 1) * 16);

    for (int t = blockIdx.x; t < NN / 128; t += gridDim.x) {
        int r0 = t * 128;
        float c[2][8][4];
        #pragma unroll
        for (int mi = 0; mi < 2; mi++)
            #pragma unroll
            for (int f = 0; f < 8; f++)
                #pragma unroll
                for (int q = 0; q < 4; q++) c[mi][f][q] = 0.f;

        #pragma unroll
        for (int kc = 0; kc < 2; kc++) {
            __syncthreads();
            const float* src = kc ? g_agg : x;
            #pragma unroll
            for (int i = tid; i < 2048; i += 256) {
                int row = i >> 4, kk = (i & 15) * 8;
                const float* gp = src + (size_t)(r0 + row) * 128 + kk;
                float4 v0 = ((const float4*)gp)[0];
                float4 v1 = ((const float4*)gp)[1];
                uint32_t h0 = pk_hi(v0.x, v0.y), h1 = pk_hi(v0.z, v0.w);
                uint32_t h2 = pk_hi(v1.x, v1.y), h3 = pk_hi(v1.z, v1.w);
                uint32_t off = (uint32_t)row * K3_AROW + (uint32_t)kk * 2;
                sts128(sb + A_HI + off, h0, h1, h2, h3);
                sts128(sb + A_LO + off,
                       pk_lo_from(h0, v0.x, v0.y), pk_lo_from(h1, v0.z, v0.w),
                       pk_lo_from(h2, v1.x, v1.y), pk_lo_from(h3, v1.z, v1.w));
            }
            __syncthreads();

            #pragma unroll
            for (int ks = 0; ks < 8; ks++) {
                uint32_t ak = (uint32_t)ks * 32;
                uint32_t bk = (uint32_t)(kc * 8 + ks) * 32;
                uint32_t ah[2][4], al[2][4], bh[4][4], bl[4][4];
                ldsm4(ah[0], sb + A_HI + aoff[0] + ak);
                ldsm4(ah[1], sb + A_HI + aoff[1] + ak);
                ldsm4(al[0], sb + A_LO + aoff[0] + ak);
                ldsm4(al[1], sb + A_LO + aoff[1] + ak);
                #pragma unroll
                for (int j2 = 0; j2 < 4; j2++) {
                    uint32_t ro = boff + (uint32_t)j2 * (16 * K3_BROW) + bk;
                    ldsm4(bh[j2], sb + B_HI + ro);
                    ldsm4(bl[j2], sb + B_LO + ro);
                }
                #pragma unroll
                for (int mi = 0; mi < 2; mi++)
                    #pragma unroll
                    for (int f = 0; f < 8; f++) {
                        uint32_t bh0 = bh[f >> 1][(f & 1) * 2], bh1 = bh[f >> 1][(f & 1) * 2 + 1];
                        uint32_t bl0 = bl[f >> 1][(f & 1) * 2], bl1 = bl[f >> 1][(f & 1) * 2 + 1];
                        mma16816(c[mi][f], ah[mi], bh0, bh1);
                        mma16816(c[mi][f], ah[mi], bl0, bl1);
                        mma16816(c[mi][f], al[mi], bh0, bh1);
                    }
            }
        }

        #pragma unroll
        for (int mi = 0; mi < 2; mi++) {
            int row = r0 + wm * 32 + mi * 16 + (lane >> 2);
            #pragma unroll
            for (int f = 0; f < 8; f++) {
                int col = wn * 64 + f * 8 + (lane & 3) * 2;
                float2 v0, v1;
                v0.x = fmaxf(c[mi][f][0] + bias[f].x, 0.f);
                v0.y = fmaxf(c[mi][f][1] + bias[f].y, 0.f);
                v1.x = fmaxf(c[mi][f][2] + bias[f].x, 0.f);
                v1.y = fmaxf(c[mi][f][3] + bias[f].y, 0.f);
                *(float2*)(out + (size_t)row * OUTF + col)       = v0;
                *(float2*)(out + (size_t)(row + 8) * OUTF + col) = v1;
            }
        }
    }
}

// ---------------------------------------------------------------------------
extern "C" void kernel_launch(void* const* d_in, const int* in_sizes, int n_in,
                              void* d_out, int out_size)
{
    const float* x     = (const float*)d_in[0];
    const float* W_s   = (const float*)d_in[1];
    const float* b_s   = (const float*)d_in[2];
    const float* W_h   = (const float*)d_in[3];
    const float* b_h   = (const float*)d_in[4];
    const float* W_out = (const float*)d_in[5];
    const float* b_out = (const float*)d_in[6];
    // d_in[7] = batch (int64) — equal-size sorted graphs; unused.
    float* out = (float*)d_out;

    cudaFuncSetAttribute(k1h,    cudaFuncAttributeMaxDynamicSharedMemorySize, H_SMEM);
    cudaFuncSetAttribute(k3_mma, cudaFuncAttributeMaxDynamicSharedMemorySize, K3_SMEM);

    k0_convW<<<80, 256>>>(W_out, W_h);
    k1s<<<NN / 32, 256>>>(x, W_s, b_s);
    k1h<<<NN / 128, 256, H_SMEM>>>(x, b_h);
    k2_knn_agg<<<NB * (LG / 8), 256>>>();
    k3_mma<<<148, 256, K3_SMEM>>>(x, b_out, out);
}

// round 14
// speedup vs baseline: 1.5593x; 1.5593x over previous
#include <cuda_runtime.h>
#include <cuda_bf16.h>
#include <math.h>
#include <stdint.h>

#define NB 64
#define LG 1024
#define NN (NB*LG)
#define KK 16
#define INF_ 128
#define OUTF 128
#define SS 4
#define FLR 64
#define FEAT 256

// Scratch (device globals: allocation is forbidden)
__device__ float g_s[NN * SS];
__device__ float g_h[NN * FLR];
__device__ float g_agg[NN * 2 * FLR];
__device__ uint32_t g_Wbhi[128 * 128];    // W_out^T bf16-hi [n][kw]
__device__ uint32_t g_Wblo[128 * 128];    // W_out^T bf16-lo
__device__ uint32_t g_Whhi[64 * 64];      // W_h^T bf16-hi [n][kw]
__device__ uint32_t g_Whlo[64 * 64];      // W_h^T bf16-lo

// ---------------------------------------------------------------------------
// helpers
// ---------------------------------------------------------------------------
__device__ __forceinline__ uint32_t s2u(const void* p) {
    uint32_t a;
    asm("{ .reg .u64 t; cvta.to.shared.u64 t, %1; cvt.u32.u64 %0, t; }" : "=r"(a) : "l"(p));
    return a;
}
__device__ __forceinline__ uint32_t pk_hi(float a, float b) {
    uint32_t p;
    asm("cvt.rn.bf16x2.f32 %0, %1, %2;" : "=r"(p) : "f"(b), "f"(a));
    return p;   // low16 = bf16(a), high16 = bf16(b)
}
__device__ __forceinline__ uint32_t pk_lo_from(uint32_t ph, float a, float b) {
    float ha = __uint_as_float(ph << 16);
    float hb = __uint_as_float(ph & 0xFFFF0000u);
    return pk_hi(a - ha, b - hb);
}
__device__ __forceinline__ void sts128(uint32_t addr, uint32_t a, uint32_t b, uint32_t c, uint32_t d) {
    asm volatile("st.shared.v4.b32 [%0], {%1,%2,%3,%4};" :: "r"(addr), "r"(a), "r"(b), "r"(c), "r"(d) : "memory");
}
__device__ __forceinline__ void ldsm4(uint32_t* r, uint32_t addr) {
    asm volatile("ldmatrix.sync.aligned.m8n8.x4.shared.b16 {%0,%1,%2,%3}, [%4];"
        : "=r"(r[0]), "=r"(r[1]), "=r"(r[2]), "=r"(r[3]) : "r"(addr));
}
__device__ __forceinline__ void mma16816(float* c, const uint32_t* a, uint32_t b0, uint32_t b1) {
    asm volatile("mma.sync.aligned.m16n8k16.row.col.f32.bf16.bf16.f32 "
        "{%0,%1,%2,%3}, {%4,%5,%6,%7}, {%8,%9}, {%0,%1,%2,%3};"
        : "+f"(c[0]), "+f"(c[1]), "+f"(c[2]), "+f"(c[3])
        : "r"(a[0]), "r"(a[1]), "r"(a[2]), "r"(a[3]), "r"(b0), "r"(b1));
}

// ---------------------------------------------------------------------------
// Kernel 0: W_out and W_h -> bf16 hi/lo splits, B layout [n][k]
// ---------------------------------------------------------------------------
__global__ __launch_bounds__(256) void k0_convW(
    const float* __restrict__ Wout, const float* __restrict__ Wh)
{
    int idx = blockIdx.x * 256 + threadIdx.x;   // 0..20479
    if (idx < 16384) {
        int n = idx >> 7, kw = idx & 127;
        float w0 = Wout[(size_t)(2 * kw) * OUTF + n];
        float w1 = Wout[(size_t)(2 * kw + 1) * OUTF + n];
        uint32_t ph = pk_hi(w0, w1);
        g_Wbhi[idx] = ph;
        g_Wblo[idx] = pk_lo_from(ph, w0, w1);
    } else {
        int i2 = idx - 16384;                   // 0..4095
        int n = i2 >> 6, kw = i2 & 63;
        float w0 = Wh[(size_t)(2 * kw) * FLR + n];
        float w1 = Wh[(size_t)(2 * kw + 1) * FLR + n];
        uint32_t ph = pk_hi(w0, w1);
        g_Whhi[i2] = ph;
        g_Whlo[i2] = pk_lo_from(ph, w0, w1);
    }
}

// ---------------------------------------------------------------------------
// Kernel 1s: s = x@W_s + b_s (fp32 exact — keeps kNN selection bit-identical).
// ---------------------------------------------------------------------------
__global__ __launch_bounds__(256) void k1s(
    const float* __restrict__ x, const float* __restrict__ Ws,
    const float* __restrict__ bs)
{
    int tid = threadIdx.x, warp = tid >> 5, lane = tid & 31;
    float4 wk0 = ((const float4*)Ws)[lane * 4 + 0];
    float4 wk1 = ((const float4*)Ws)[lane * 4 + 1];
    float4 wk2 = ((const float4*)Ws)[lane * 4 + 2];
    float4 wk3 = ((const float4*)Ws)[lane * 4 + 3];
    float4 bsv = *(const float4*)bs;

    int row0 = (blockIdx.x * 8 + warp) * 4;
    #pragma unroll
    for (int r = 0; r < 4; r++) {
        int row = row0 + r;
        float4 xv = ((const float4*)(x + (size_t)row * INF_))[lane];
        float4 a;
        a.x = xv.x * wk0.x; a.y = xv.x * wk0.y; a.z = xv.x * wk0.z; a.w = xv.x * wk0.w;
        a.x = fmaf(xv.y, wk1.x, a.x); a.y = fmaf(xv.y, wk1.y, a.y);
        a.z = fmaf(xv.y, wk1.z, a.z); a.w = fmaf(xv.y, wk1.w, a.w);
        a.x = fmaf(xv.z, wk2.x, a.x); a.y = fmaf(xv.z, wk2.y, a.y);
        a.z = fmaf(xv.z, wk2.z, a.z); a.w = fmaf(xv.z, wk2.w, a.w);
        a.x = fmaf(xv.w, wk3.x, a.x); a.y = fmaf(xv.w, wk3.y, a.y);
        a.z = fmaf(xv.w, wk3.z, a.z); a.w = fmaf(xv.w, wk3.w, a.w);
        #pragma unroll
        for (int off = 16; off; off >>= 1) {
            a.x += __shfl_xor_sync(0xffffffffu, a.x, off);
            a.y += __shfl_xor_sync(0xffffffffu, a.y, off);
            a.z += __shfl_xor_sync(0xffffffffu, a.z, off);
            a.w += __shfl_xor_sync(0xffffffffu, a.w, off);
        }
        if (lane == 0) {
            float4 o;
            o.x = a.x + bsv.x; o.y = a.y + bsv.y;
            o.z = a.z + bsv.z; o.w = a.w + bsv.w;
            ((float4*)g_s)[row] = o;
        }
    }
}

// ---------------------------------------------------------------------------
// Kernel 1h: h = x@W_h + b_h via HMMA bf16x3 (unchanged from R13).
// ---------------------------------------------------------------------------
#define H_AROW 272
#define H_BROW 272
#define H_AHI  0
#define H_ALO  34816
#define H_BHI  69632
#define H_BLO  87040
#define H_SMEM 104448

__global__ __launch_bounds__(256, 1) void k1h(
    const float* __restrict__ x, const float* __restrict__ bh)
{
    extern __shared__ __align__(16) char smem[];
    uint32_t sb = s2u(smem);
    int tid = threadIdx.x, warp = tid >> 5, lane = tid & 31;
    int wm = warp >> 1, wn = warp & 1;
    int r0 = blockIdx.x * 128;

    #pragma unroll
    for (int i = tid; i < 1024; i += 256) {
        uint4 vh = ((const uint4*)g_Whhi)[i];
        uint4 vl = ((const uint4*)g_Whlo)[i];
        int n = i >> 4, c = i & 15;
        uint32_t off = (uint32_t)n * H_BROW + (uint32_t)c * 16;
        sts128(sb + H_BHI + off, vh.x, vh.y, vh.z, vh.w);
        sts128(sb + H_BLO + off, vl.x, vl.y, vl.z, vl.w);
    }

    #pragma unroll
    for (int i = tid; i < 2048; i += 256) {
        int row = i >> 4, kk = (i & 15) * 8;
        const float* gp = x + (size_t)(r0 + row) * 128 + kk;
        float4 v0 = ((const float4*)gp)[0];
        float4 v1 = ((const float4*)gp)[1];
        uint32_t h0 = pk_hi(v0.x, v0.y), h1 = pk_hi(v0.z, v0.w);
        uint32_t h2 = pk_hi(v1.x, v1.y), h3 = pk_hi(v1.z, v1.w);
        uint32_t off = (uint32_t)row * H_AROW + (uint32_t)kk * 2;
        sts128(sb + H_AHI + off, h0, h1, h2, h3);
        sts128(sb + H_ALO + off,
               pk_lo_from(h0, v0.x, v0.y), pk_lo_from(h1, v0.z, v0.w),
               pk_lo_from(h2, v1.x, v1.y), pk_lo_from(h3, v1.z, v1.w));
    }
    __syncthreads();

    uint32_t aoff[2];
    #pragma unroll
    for (int mi = 0; mi < 2; mi++)
        aoff[mi] = (uint32_t)(wm * 32 + mi * 16 + (lane & 15)) * H_AROW
                 + (uint32_t)((lane >> 4) * 16);
    uint32_t boff = (uint32_t)(wn * 32 + (lane & 7) + ((lane >> 4) << 3)) * H_BROW
                  + (uint32_t)(((lane >> 3) & 1) * 16);

    float c[2][4][4];
    #pragma unroll
    for (int mi = 0; mi < 2; mi++)
        #pragma unroll
        for (int f = 0; f < 4; f++)
            #pragma unroll
            for (int q = 0; q < 4; q++) c[mi][f][q] = 0.f;

    #pragma unroll
    for (int ks = 0; ks < 8; ks++) {
        uint32_t kb = (uint32_t)ks * 32;
        uint32_t ah[2][4], al[2][4], bhf[2][4], blf[2][4];
        ldsm4(ah[0], sb + H_AHI + aoff[0] + kb);
        ldsm4(ah[1], sb + H_AHI + aoff[1] + kb);
        ldsm4(al[0], sb + H_ALO + aoff[0] + kb);
        ldsm4(al[1], sb + H_ALO + aoff[1] + kb);
        #pragma unroll
        for (int j2 = 0; j2 < 2; j2++) {
            uint32_t ro = boff + (uint32_t)j2 * (16 * H_BROW) + kb;
            ldsm4(bhf[j2], sb + H_BHI + ro);
            ldsm4(blf[j2], sb + H_BLO + ro);
        }
        #pragma unroll
        for (int mi = 0; mi < 2; mi++)
            #pragma unroll
            for (int f = 0; f < 4; f++) {
                uint32_t b0 = bhf[f >> 1][(f & 1) * 2], b1 = bhf[f >> 1][(f & 1) * 2 + 1];
                uint32_t l0 = blf[f >> 1][(f & 1) * 2], l1 = blf[f >> 1][(f & 1) * 2 + 1];
                mma16816(c[mi][f], ah[mi], b0, b1);
                mma16816(c[mi][f], ah[mi], l0, l1);
                mma16816(c[mi][f], al[mi], b0, b1);
            }
    }

    #pragma unroll
    for (int mi = 0; mi < 2; mi++) {
        int row = r0 + wm * 32 + mi * 16 + (lane >> 2);
        #pragma unroll
        for (int f = 0; f < 4; f++) {
            int col = wn * 32 + f * 8 + (lane & 3) * 2;
            float2 bv = *(const float2*)(bh + col);
            float2 v0, v1;
            v0.x = c[mi][f][0] + bv.x; v0.y = c[mi][f][1] + bv.y;
            v1.x = c[mi][f][2] + bv.x; v1.y = c[mi][f][3] + bv.y;
            *(float2*)(g_h + (size_t)row * FLR + col)       = v0;
            *(float2*)(g_h + (size_t)(row + 8) * FLR + col) = v1;
        }
    }
}

// ---------------------------------------------------------------------------
// Kernel 2: per-graph kNN + aggregate. NEW selection:
//   Tp = 16th smallest of the 32 lane-minima (bitonic-32). Since the 16
//   smallest lane-minima lanes each contribute >=1 element <= Tp, the
//   candidate set {u <= Tp} has >=16 elements and contains the true top-16.
//   One ballot-compaction -> pair-bitonic sort of (u, j) -> lanes 0..15 hold
//   the exact stable top-16 ascending. Rare cnt>32 -> exact fallback.
// ---------------------------------------------------------------------------
__global__ __launch_bounds__(256) void k2_knn_agg()
{
    __shared__ float4   s_sh[LG];
    __shared__ float    sq_sh[LG];
    __shared__ unsigned cu[8][32];
    __shared__ int      cj[8][32];
    __shared__ int      sel_j[8][KK];
    __shared__ float    sel_d[8][KK];

    int g  = blockIdx.x >> 7;
    int nb = blockIdx.x & 127;
    int tid = threadIdx.x, warp = tid >> 5, lane = tid & 31;
    int gbase = g * LG;

    const float4* sg = (const float4*)(g_s + (size_t)gbase * SS);
    for (int i = tid; i < LG; i += 256) {
        float4 v = sg[i];
        s_sh[i] = v;
        sq_sh[i] = v.x*v.x + v.y*v.y + v.z*v.z + v.w*v.w;
    }
    __syncthreads();

    int li = nb * 8 + warp;
    float4 si = s_sh[li];
    float sqi = sq_sh[li];

    unsigned u[32];
    #pragma unroll
    for (int c = 0; c < 32; c++) {
        int j = (c << 5) | lane;
        float4 sj = s_sh[j];
        float dot = si.x*sj.x + si.y*sj.y + si.z*sj.z + si.w*sj.w;
        float v = fmaxf(sqi + sq_sh[j] - 2.f * dot, 0.f);
        u[c] = __float_as_uint(v);   // positive floats: uint order == float order
    }

    // ---- lane minimum ----
    unsigned lmin = u[0];
    #pragma unroll
    for (int c = 1; c < 32; c++) lmin = min(lmin, u[c]);

    // ---- bitonic-32 ascending sort of lane minima; Tp = sorted[15] ----
    unsigned v = lmin;
    #pragma unroll
    for (int k = 2; k <= 32; k <<= 1) {
        #pragma unroll
        for (int j2 = k >> 1; j2; j2 >>= 1) {
            unsigned o = __shfl_xor_sync(0xffffffffu, v, j2);
            bool keepmin = (((lane & j2) == 0) != ((lane & k) != 0));
            unsigned mn = min(v, o), mx = max(v, o);
            v = keepmin ? mn : mx;
        }
    }
    unsigned Tp = __shfl_sync(0xffffffffu, v, 15);

    // ---- compact candidates u <= Tp (ascending j) ----
    int cbase = 0;
    unsigned lmask = (1u << lane) - 1u;
    #pragma unroll
    for (int c = 0; c < 32; c++) {
        bool p = (u[c] <= Tp);
        unsigned m = __ballot_sync(0xffffffffu, p);
        if (p) {
            int pos = cbase + __popc(m & lmask);
            if (pos < 32) { cu[warp][pos] = u[c]; cj[warp][pos] = (c << 5) | lane; }
        }
        cbase += __popc(m);
    }
    __syncwarp();

    if (cbase > 32) {
        // ---- rare exact fallback: successor-trick T, recompact ----
        unsigned base2 = 0;
        #pragma unroll 1
        for (int t = 0; t < KK; t++) {
            unsigned m2 = 0xFFFFFFFFu;
            #pragma unroll
            for (int c = 0; c < 32; c++) m2 = min(m2, u[c] - base2);
            #pragma unroll
            for (int off = 16; off; off >>= 1)
                m2 = min(m2, __shfl_xor_sync(0xffffffffu, m2, off));
            base2 += m2 + 1u;
        }
        unsigned Tt = base2 - 1u;
        int cb2 = 0;
        #pragma unroll
        for (int c = 0; c < 32; c++) {
            bool p = (u[c] <= Tt);
            unsigned m = __ballot_sync(0xffffffffu, p);
            if (p) {
                int pos = cb2 + __popc(m & lmask);
                if (pos < 32) { cu[warp][pos] = u[c]; cj[warp][pos] = (c << 5) | lane; }
            }
            cb2 += __popc(m);
        }
        cbase = cb2;
        __syncwarp();
    }

    // ---- pair bitonic sort (u asc, tie: j asc) across lanes ----
    unsigned su = (lane < cbase) ? cu[warp][lane] : 0xFFFFFFFFu;
    int      sj = (lane < cbase) ? cj[warp][lane] : 0x7FFFFFFF;
    #pragma unroll
    for (int k = 2; k <= 32; k <<= 1) {
        #pragma unroll
        for (int j2 = k >> 1; j2; j2 >>= 1) {
            unsigned ou = __shfl_xor_sync(0xffffffffu, su, j2);
            int      oj = __shfl_xor_sync(0xffffffffu, sj, j2);
            bool keepmin = (((lane & j2) == 0) != ((lane & k) != 0));
            bool oless = (ou < su) || (ou == su && oj < sj);
            if (keepmin == oless) { su = ou; sj = oj; }
        }
    }
    if (lane < KK) {
        sel_j[warp][lane] = sj;
        sel_d[warp][lane] = __uint_as_float(su);
    }
    __syncwarp();

    // ---- gather + weighted mean/max (ascending-distance order == reference) ----
    float m0 = 0.f, m1 = 0.f, x0 = -3.4e38f, x1 = -3.4e38f;
    #pragma unroll 4
    for (int t = 0; t < KK; t++) {
        int   j  = sel_j[warp][t];
        float wt = __expf(-10.f * sel_d[warp][t]);
        const float* hp = g_h + (size_t)(gbase + j) * FLR;
        float v0 = hp[lane]      * wt;
        float v1 = hp[lane + 32] * wt;
        m0 += v0; m1 += v1;
        x0 = fmaxf(x0, v0); x1 = fmaxf(x1, v1);
    }
    float* ap = g_agg + (size_t)(gbase + li) * (2 * FLR);
    ap[lane]      = m0 * (1.f / 16.f);
    ap[lane + 32] = m1 * (1.f / 16.f);
    ap[64 + lane] = x0;
    ap[96 + lane] = x1;
}

// ---------------------------------------------------------------------------
// Kernel 3 (unchanged): HMMA bf16x3 GEMM for the output layer.
// ---------------------------------------------------------------------------
#define K3_AROW 272
#define K3_BROW 528
#define A_HI    0
#define A_LO    34816
#define B_HI    69632
#define B_LO    137216
#define K3_SMEM 204800

__global__ __launch_bounds__(256, 1) void k3_mma(
    const float* __restrict__ x,
    const float* __restrict__ bout,
    float* __restrict__ out)
{
    extern __shared__ __align__(16) char smem[];
    uint32_t sb = s2u(smem);
    int tid = threadIdx.x, warp = tid >> 5, lane = tid & 31;
    int wm = warp >> 1, wn = warp & 1;

    #pragma unroll 4
    for (int i = tid; i < 4096; i += 256) {
        uint4 vh = ((const uint4*)g_Wbhi)[i];
        uint4 vl = ((const uint4*)g_Wblo)[i];
        int n = i >> 5, c = i & 31;
        uint32_t off = (uint32_t)n * K3_BROW + (uint32_t)c * 16;
        sts128(sb + B_HI + off, vh.x, vh.y, vh.z, vh.w);
        sts128(sb + B_LO + off, vl.x, vl.y, vl.z, vl.w);
    }

    float2 bias[8];
    #pragma unroll
    for (int f = 0; f < 8; f++)
        bias[f] = *(const float2*)(bout + wn * 64 + f * 8 + (lane & 3) * 2);

    uint32_t aoff[2];
    #pragma unroll
    for (int mi = 0; mi < 2; mi++)
        aoff[mi] = (uint32_t)(wm * 32 + mi * 16 + (lane & 15)) * K3_AROW
                 + (uint32_t)((lane >> 4) * 16);
    uint32_t boff = (uint32_t)(wn * 64 + (lane & 7) + ((lane >> 4) << 3)) * K3_BROW
                  + (uint32_t)(((lane >> 3) & 1) * 16);

    for (int t = blockIdx.x; t < NN / 128; t += gridDim.x) {
        int r0 = t * 128;
        float c[2][8][4];
        #pragma unroll
        for (int mi = 0; mi < 2; mi++)
            #pragma unroll
            for (int f = 0; f < 8; f++)
                #pragma unroll
                for (int q = 0; q < 4; q++) c[mi][f][q] = 0.f;

        #pragma unroll
        for (int kc = 0; kc < 2; kc++) {
            __syncthreads();
            const float* src = kc ? g_agg : x;
            #pragma unroll
            for (int i = tid; i < 2048; i += 256) {
                int row = i >> 4, kk = (i & 15) * 8;
                const float* gp = src + (size_t)(r0 + row) * 128 + kk;
                float4 v0 = ((const float4*)gp)[0];
                float4 v1 = ((const float4*)gp)[1];
                uint32_t h0 = pk_hi(v0.x, v0.y), h1 = pk_hi(v0.z, v0.w);
                uint32_t h2 = pk_hi(v1.x, v1.y), h3 = pk_hi(v1.z, v1.w);
                uint32_t off = (uint32_t)row * K3_AROW + (uint32_t)kk * 2;
                sts128(sb + A_HI + off, h0, h1, h2, h3);
                sts128(sb + A_LO + off,
                       pk_lo_from(h0, v0.x, v0.y), pk_lo_from(h1, v0.z, v0.w),
                       pk_lo_from(h2, v1.x, v1.y), pk_lo_from(h3, v1.z, v1.w));
            }
            __syncthreads();

            #pragma unroll
            for (int ks = 0; ks < 8; ks++) {
                uint32_t ak = (uint32_t)ks * 32;
                uint32_t bk = (uint32_t)(kc * 8 + ks) * 32;
                uint32_t ah[2][4], al[2][4], bh[4][4], bl[4][4];
                ldsm4(ah[0], sb + A_HI + aoff[0] + ak);
                ldsm4(ah[1], sb + A_HI + aoff[1] + ak);
                ldsm4(al[0], sb + A_LO + aoff[0] + ak);
                ldsm4(al[1], sb + A_LO + aoff[1] + ak);
                #pragma unroll
                for (int j2 = 0; j2 < 4; j2++) {
                    uint32_t ro = boff + (uint32_t)j2 * (16 * K3_BROW) + bk;
                    ldsm4(bh[j2], sb + B_HI + ro);
                    ldsm4(bl[j2], sb + B_LO + ro);
                }
                #pragma unroll
                for (int mi = 0; mi < 2; mi++)
                    #pragma unroll
                    for (int f = 0; f < 8; f++) {
                        uint32_t bh0 = bh[f >> 1][(f & 1) * 2], bh1 = bh[f >> 1][(f & 1) * 2 + 1];
                        uint32_t bl0 = bl[f >> 1][(f & 1) * 2], bl1 = bl[f >> 1][(f & 1) * 2 + 1];
                        mma16816(c[mi][f], ah[mi], bh0, bh1);
                        mma16816(c[mi][f], ah[mi], bl0, bl1);
                        mma16816(c[mi][f], al[mi], bh0, bh1);
                    }
            }
        }

        #pragma unroll
        for (int mi = 0; mi < 2; mi++) {
            int row = r0 + wm * 32 + mi * 16 + (lane >> 2);
            #pragma unroll
            for (int f = 0; f < 8; f++) {
                int col = wn * 64 + f * 8 + (lane & 3) * 2;
                float2 v0, v1;
                v0.x = fmaxf(c[mi][f][0] + bias[f].x, 0.f);
                v0.y = fmaxf(c[mi][f][1] + bias[f].y, 0.f);
                v1.x = fmaxf(c[mi][f][2] + bias[f].x, 0.f);
                v1.y = fmaxf(c[mi][f][3] + bias[f].y, 0.f);
                *(float2*)(out + (size_t)row * OUTF + col)       = v0;
                *(float2*)(out + (size_t)(row + 8) * OUTF + col) = v1;
            }
        }
    }
}

// ---------------------------------------------------------------------------
extern "C" void kernel_launch(void* const* d_in, const int* in_sizes, int n_in,
                              void* d_out, int out_size)
{
    const float* x     = (const float*)d_in[0];
    const float* W_s   = (const float*)d_in[1];
    const float* b_s   = (const float*)d_in[2];
    const float* W_h   = (const float*)d_in[3];
    const float* b_h   = (const float*)d_in[4];
    const float* W_out = (const float*)d_in[5];
    const float* b_out = (const float*)d_in[6];
    // d_in[7] = batch (int64) — equal-size sorted graphs; unused.
    float* out = (float*)d_out;

    cudaFuncSetAttribute(k1h,    cudaFuncAttributeMaxDynamicSharedMemorySize, H_SMEM);
    cudaFuncSetAttribute(k3_mma, cudaFuncAttributeMaxDynamicSharedMemorySize, K3_SMEM);

    k0_convW<<<80, 256>>>(W_out, W_h);
    k1s<<<NN / 32, 256>>>(x, W_s, b_s);
    k1h<<<NN / 128, 256, H_SMEM>>>(x, b_h);
    k2_knn_agg<<<NB * (LG / 8), 256>>>();
    k3_mma<<<148, 256, K3_SMEM>>>(x, b_out, out);
}

// round 15
// speedup vs baseline: 1.5716x; 1.0079x over previous
#include <cuda_runtime.h>
#include <cuda_bf16.h>
#include <math.h>
#include <stdint.h>

#define NB 64
#define LG 1024
#define NN (NB*LG)
#define KK 16
#define INF_ 128
#define OUTF 128
#define SS 4
#define FLR 64
#define FEAT 256

// Scratch (device globals: allocation is forbidden)
__device__ float g_s[NN * SS];
__device__ float g_h[NN * FLR];
__device__ float g_agg[NN * 2 * FLR];
__device__ uint32_t g_Wbhi[128 * 128];    // W_out^T bf16-hi [n][kw]
__device__ uint32_t g_Wblo[128 * 128];    // W_out^T bf16-lo
__device__ uint32_t g_Whhi[64 * 64];      // W_h^T bf16-hi [n][kw]
__device__ uint32_t g_Whlo[64 * 64];      // W_h^T bf16-lo

// ---------------------------------------------------------------------------
// helpers
// ---------------------------------------------------------------------------
__device__ __forceinline__ uint32_t s2u(const void* p) {
    uint32_t a;
    asm("{ .reg .u64 t; cvta.to.shared.u64 t, %1; cvt.u32.u64 %0, t; }" : "=r"(a) : "l"(p));
    return a;
}
__device__ __forceinline__ uint32_t pk_hi(float a, float b) {
    uint32_t p;
    asm("cvt.rn.bf16x2.f32 %0, %1, %2;" : "=r"(p) : "f"(b), "f"(a));
    return p;   // low16 = bf16(a), high16 = bf16(b)
}
__device__ __forceinline__ uint32_t pk_lo_from(uint32_t ph, float a, float b) {
    float ha = __uint_as_float(ph << 16);
    float hb = __uint_as_float(ph & 0xFFFF0000u);
    return pk_hi(a - ha, b - hb);
}
__device__ __forceinline__ void sts128(uint32_t addr, uint32_t a, uint32_t b, uint32_t c, uint32_t d) {
    asm volatile("st.shared.v4.b32 [%0], {%1,%2,%3,%4};" :: "r"(addr), "r"(a), "r"(b), "r"(c), "r"(d) : "memory");
}
__device__ __forceinline__ void ldsm4(uint32_t* r, uint32_t addr) {
    asm volatile("ldmatrix.sync.aligned.m8n8.x4.shared.b16 {%0,%1,%2,%3}, [%4];"
        : "=r"(r[0]), "=r"(r[1]), "=r"(r[2]), "=r"(r[3]) : "r"(addr));
}
__device__ __forceinline__ void mma16816(float* c, const uint32_t* a, uint32_t b0, uint32_t b1) {
    asm volatile("mma.sync.aligned.m16n8k16.row.col.f32.bf16.bf16.f32 "
        "{%0,%1,%2,%3}, {%4,%5,%6,%7}, {%8,%9}, {%0,%1,%2,%3};"
        : "+f"(c[0]), "+f"(c[1]), "+f"(c[2]), "+f"(c[3])
        : "r"(a[0]), "r"(a[1]), "r"(a[2]), "r"(a[3]), "r"(b0), "r"(b1));
}
// packed fp32 pair ops (sm_100+ baseline PTX)
__device__ __forceinline__ uint64_t f2fma(uint64_t a, uint64_t b, uint64_t c) {
    uint64_t d;
    asm("fma.rn.f32x2 %0, %1, %2, %3;" : "=l"(d) : "l"(a), "l"(b), "l"(c));
    return d;
}
__device__ __forceinline__ uint64_t f2add(uint64_t a, uint64_t b) {
    uint64_t d;
    asm("add.rn.f32x2 %0, %1, %2;" : "=l"(d) : "l"(a), "l"(b));
    return d;
}
__device__ __forceinline__ uint64_t fpack(float a, float b) {
    uint64_t d;
    asm("mov.b64 %0, {%1, %2};" : "=l"(d) : "f"(a), "f"(b));
    return d;
}
__device__ __forceinline__ void funpack(float& a, float& b, uint64_t p) {
    asm("mov.b64 {%0, %1}, %2;" : "=f"(a), "=f"(b) : "l"(p));
}
__device__ __forceinline__ void lds2u64(uint64_t& a, uint64_t& b, uint32_t addr) {
    asm volatile("ld.shared.v2.u64 {%0, %1}, [%2];" : "=l"(a), "=l"(b) : "r"(addr));
}

// ---------------------------------------------------------------------------
// Kernel 0: W_out and W_h -> bf16 hi/lo splits, B layout [n][k]
// ---------------------------------------------------------------------------
__global__ __launch_bounds__(256) void k0_convW(
    const float* __restrict__ Wout, const float* __restrict__ Wh)
{
    int idx = blockIdx.x * 256 + threadIdx.x;   // 0..20479
    if (idx < 16384) {
        int n = idx >> 7, kw = idx & 127;
        float w0 = Wout[(size_t)(2 * kw) * OUTF + n];
        float w1 = Wout[(size_t)(2 * kw + 1) * OUTF + n];
        uint32_t ph = pk_hi(w0, w1);
        g_Wbhi[idx] = ph;
        g_Wblo[idx] = pk_lo_from(ph, w0, w1);
    } else {
        int i2 = idx - 16384;                   // 0..4095
        int n = i2 >> 6, kw = i2 & 63;
        float w0 = Wh[(size_t)(2 * kw) * FLR + n];
        float w1 = Wh[(size_t)(2 * kw + 1) * FLR + n];
        uint32_t ph = pk_hi(w0, w1);
        g_Whhi[i2] = ph;
        g_Whlo[i2] = pk_lo_from(ph, w0, w1);
    }
}

// ---------------------------------------------------------------------------
// Kernel 1s: s = x@W_s + b_s (fp32 exact — kNN selection bit-identical).
// ---------------------------------------------------------------------------
__global__ __launch_bounds__(256) void k1s(
    const float* __restrict__ x, const float* __restrict__ Ws,
    const float* __restrict__ bs)
{
    int tid = threadIdx.x, warp = tid >> 5, lane = tid & 31;
    float4 wk0 = ((const float4*)Ws)[lane * 4 + 0];
    float4 wk1 = ((const float4*)Ws)[lane * 4 + 1];
    float4 wk2 = ((const float4*)Ws)[lane * 4 + 2];
    float4 wk3 = ((const float4*)Ws)[lane * 4 + 3];
    float4 bsv = *(const float4*)bs;

    int row0 = (blockIdx.x * 8 + warp) * 4;
    #pragma unroll
    for (int r = 0; r < 4; r++) {
        int row = row0 + r;
        float4 xv = ((const float4*)(x + (size_t)row * INF_))[lane];
        float4 a;
        a.x = xv.x * wk0.x; a.y = xv.x * wk0.y; a.z = xv.x * wk0.z; a.w = xv.x * wk0.w;
        a.x = fmaf(xv.y, wk1.x, a.x); a.y = fmaf(xv.y, wk1.y, a.y);
        a.z = fmaf(xv.y, wk1.z, a.z); a.w = fmaf(xv.y, wk1.w, a.w);
        a.x = fmaf(xv.z, wk2.x, a.x); a.y = fmaf(xv.z, wk2.y, a.y);
        a.z = fmaf(xv.z, wk2.z, a.z); a.w = fmaf(xv.z, wk2.w, a.w);
        a.x = fmaf(xv.w, wk3.x, a.x); a.y = fmaf(xv.w, wk3.y, a.y);
        a.z = fmaf(xv.w, wk3.z, a.z); a.w = fmaf(xv.w, wk3.w, a.w);
        #pragma unroll
        for (int off = 16; off; off >>= 1) {
            a.x += __shfl_xor_sync(0xffffffffu, a.x, off);
            a.y += __shfl_xor_sync(0xffffffffu, a.y, off);
            a.z += __shfl_xor_sync(0xffffffffu, a.z, off);
            a.w += __shfl_xor_sync(0xffffffffu, a.w, off);
        }
        if (lane == 0) {
            float4 o;
            o.x = a.x + bsv.x; o.y = a.y + bsv.y;
            o.z = a.z + bsv.z; o.w = a.w + bsv.w;
            ((float4*)g_s)[row] = o;
        }
    }
}

// ---------------------------------------------------------------------------
// Kernel 1h: h = x@W_h + b_h via HMMA bf16x3 (unchanged).
// ---------------------------------------------------------------------------
#define H_AROW 272
#define H_BROW 272
#define H_AHI  0
#define H_ALO  34816
#define H_BHI  69632
#define H_BLO  87040
#define H_SMEM 104448

__global__ __launch_bounds__(256, 1) void k1h(
    const float* __restrict__ x, const float* __restrict__ bh)
{
    extern __shared__ __align__(16) char smem[];
    uint32_t sb = s2u(smem);
    int tid = threadIdx.x, warp = tid >> 5, lane = tid & 31;
    int wm = warp >> 1, wn = warp & 1;
    int r0 = blockIdx.x * 128;

    #pragma unroll
    for (int i = tid; i < 1024; i += 256) {
        uint4 vh = ((const uint4*)g_Whhi)[i];
        uint4 vl = ((const uint4*)g_Whlo)[i];
        int n = i >> 4, c = i & 15;
        uint32_t off = (uint32_t)n * H_BROW + (uint32_t)c * 16;
        sts128(sb + H_BHI + off, vh.x, vh.y, vh.z, vh.w);
        sts128(sb + H_BLO + off, vl.x, vl.y, vl.z, vl.w);
    }

    #pragma unroll
    for (int i = tid; i < 2048; i += 256) {
        int row = i >> 4, kk = (i & 15) * 8;
        const float* gp = x + (size_t)(r0 + row) * 128 + kk;
        float4 v0 = ((const float4*)gp)[0];
        float4 v1 = ((const float4*)gp)[1];
        uint32_t h0 = pk_hi(v0.x, v0.y), h1 = pk_hi(v0.z, v0.w);
        uint32_t h2 = pk_hi(v1.x, v1.y), h3 = pk_hi(v1.z, v1.w);
        uint32_t off = (uint32_t)row * H_AROW + (uint32_t)kk * 2;
        sts128(sb + H_AHI + off, h0, h1, h2, h3);
        sts128(sb + H_ALO + off,
               pk_lo_from(h0, v0.x, v0.y), pk_lo_from(h1, v0.z, v0.w),
               pk_lo_from(h2, v1.x, v1.y), pk_lo_from(h3, v1.z, v1.w));
    }
    __syncthreads();

    uint32_t aoff[2];
    #pragma unroll
    for (int mi = 0; mi < 2; mi++)
        aoff[mi] = (uint32_t)(wm * 32 + mi * 16 + (lane & 15)) * H_AROW
                 + (uint32_t)((lane >> 4) * 16);
    uint32_t boff = (uint32_t)(wn * 32 + (lane & 7) + ((lane >> 4) << 3)) * H_BROW
                  + (uint32_t)(((lane >> 3) & 1) * 16);

    float c[2][4][4];
    #pragma unroll
    for (int mi = 0; mi < 2; mi++)
        #pragma unroll
        for (int f = 0; f < 4; f++)
            #pragma unroll
            for (int q = 0; q < 4; q++) c[mi][f][q] = 0.f;

    #pragma unroll
    for (int ks = 0; ks < 8; ks++) {
        uint32_t kb = (uint32_t)ks * 32;
        uint32_t ah[2][4], al[2][4], bhf[2][4], blf[2][4];
        ldsm4(ah[0], sb + H_AHI + aoff[0] + kb);
        ldsm4(ah[1], sb + H_AHI + aoff[1] + kb);
        ldsm4(al[0], sb + H_ALO + aoff[0] + kb);
        ldsm4(al[1], sb + H_ALO + aoff[1] + kb);
        #pragma unroll
        for (int j2 = 0; j2 < 2; j2++) {
            uint32_t ro = boff + (uint32_t)j2 * (16 * H_BROW) + kb;
            ldsm4(bhf[j2], sb + H_BHI + ro);
            ldsm4(blf[j2], sb + H_BLO + ro);
        }
        #pragma unroll
        for (int mi = 0; mi < 2; mi++)
            #pragma unroll
            for (int f = 0; f < 4; f++) {
                uint32_t b0 = bhf[f >> 1][(f & 1) * 2], b1 = bhf[f >> 1][(f & 1) * 2 + 1];
                uint32_t l0 = blf[f >> 1][(f & 1) * 2], l1 = blf[f >> 1][(f & 1) * 2 + 1];
                mma16816(c[mi][f], ah[mi], b0, b1);
                mma16816(c[mi][f], ah[mi], l0, l1);
                mma16816(c[mi][f], al[mi], b0, b1);
            }
    }

    #pragma unroll
    for (int mi = 0; mi < 2; mi++) {
        int row = r0 + wm * 32 + mi * 16 + (lane >> 2);
        #pragma unroll
        for (int f = 0; f < 4; f++) {
            int col = wn * 32 + f * 8 + (lane & 3) * 2;
            float2 bv = *(const float2*)(bh + col);
            float2 v0, v1;
            v0.x = c[mi][f][0] + bv.x; v0.y = c[mi][f][1] + bv.y;
            v1.x = c[mi][f][2] + bv.x; v1.y = c[mi][f][3] + bv.y;
            *(float2*)(g_h + (size_t)row * FLR + col)       = v0;
            *(float2*)(g_h + (size_t)(row + 8) * FLR + col) = v1;
        }
    }
}

// ---------------------------------------------------------------------------
// Kernel 2: per-graph kNN + aggregate.
// d2 via packed f32x2 FMA over SoA shared (prescaled by -2):
//   d2[j] = max((sq_j + sum_d (-2 s_j)·s_i) + sq_i, 0)
// Lane handles j = sbk*128 + lane*4 + q (q<4) — vector loads conflict-free.
// Selection: Tp = 16th of 32 lane-minima (bitonic), compaction, pair-sort.
// ---------------------------------------------------------------------------
__global__ __launch_bounds__(256) void k2_knn_agg()
{
    __shared__ float sxA[LG], syA[LG], szA[LG], swA[LG], sqA[LG];
    __shared__ unsigned cu[8][32];
    __shared__ int      cj[8][32];
    __shared__ int      sel_j[8][KK];
    __shared__ float    sel_d[8][KK];

    int g  = blockIdx.x >> 7;
    int nb = blockIdx.x & 127;
    int tid = threadIdx.x, warp = tid >> 5, lane = tid & 31;
    int gbase = g * LG;

    const float4* sg = (const float4*)(g_s + (size_t)gbase * SS);
    for (int i = tid; i < LG; i += 256) {
        float4 v = sg[i];
        sqA[i] = v.x*v.x + v.y*v.y + v.z*v.z + v.w*v.w;
        sxA[i] = -2.f * v.x; syA[i] = -2.f * v.y;
        szA[i] = -2.f * v.z; swA[i] = -2.f * v.w;
    }
    __syncthreads();

    int li = nb * 8 + warp;
    float six = -0.5f * sxA[li], siy = -0.5f * syA[li];
    float siz = -0.5f * szA[li], siw = -0.5f * swA[li];
    float sqi = sqA[li];
    uint64_t six2 = fpack(six, six), siy2 = fpack(siy, siy);
    uint64_t siz2 = fpack(siz, siz), siw2 = fpack(siw, siw);
    uint64_t sqi2 = fpack(sqi, sqi);

    uint32_t bx = s2u(sxA), by = s2u(syA), bz = s2u(szA), bw = s2u(swA), bq = s2u(sqA);
    uint32_t lo = (uint32_t)lane * 16;

    unsigned u[32];
    #pragma unroll
    for (int sbk = 0; sbk < 8; sbk++) {
        uint32_t off = (uint32_t)sbk * 512 + lo;
        uint64_t x01, x23, y01, y23, z01, z23, w01, w23, q01, q23;
        lds2u64(x01, x23, bx + off);
        lds2u64(y01, y23, by + off);
        lds2u64(z01, z23, bz + off);
        lds2u64(w01, w23, bw + off);
        lds2u64(q01, q23, bq + off);
        uint64_t a01 = f2fma(x01, six2, q01);
        uint64_t a23 = f2fma(x23, six2, q23);
        a01 = f2fma(y01, siy2, a01);  a23 = f2fma(y23, siy2, a23);
        a01 = f2fma(z01, siz2, a01);  a23 = f2fma(z23, siz2, a23);
        a01 = f2fma(w01, siw2, a01);  a23 = f2fma(w23, siw2, a23);
        a01 = f2add(a01, sqi2);       a23 = f2add(a23, sqi2);
        float f0, f1, f2v, f3v;
        funpack(f0, f1, a01);
        funpack(f2v, f3v, a23);
        u[sbk*4+0] = __float_as_uint(fmaxf(f0, 0.f));
        u[sbk*4+1] = __float_as_uint(fmaxf(f1, 0.f));
        u[sbk*4+2] = __float_as_uint(fmaxf(f2v, 0.f));
        u[sbk*4+3] = __float_as_uint(fmaxf(f3v, 0.f));
    }

    // ---- lane minimum ----
    unsigned lmin = u[0];
    #pragma unroll
    for (int c = 1; c < 32; c++) lmin = min(lmin, u[c]);

    // ---- bitonic-32 ascending sort of lane minima; Tp = sorted[15] ----
    unsigned v = lmin;
    #pragma unroll
    for (int k = 2; k <= 32; k <<= 1) {
        #pragma unroll
        for (int j2 = k >> 1; j2; j2 >>= 1) {
            unsigned o = __shfl_xor_sync(0xffffffffu, v, j2);
            bool keepmin = (((lane & j2) == 0) != ((lane & k) != 0));
            unsigned mn = min(v, o), mx = max(v, o);
            v = keepmin ? mn : mx;
        }
    }
    unsigned Tp = __shfl_sync(0xffffffffu, v, 15);

    // ---- compact candidates u <= Tp ----
    int cbase = 0;
    unsigned lmask = (1u << lane) - 1u;
    #pragma unroll
    for (int c = 0; c < 32; c++) {
        bool p = (u[c] <= Tp);
        unsigned m = __ballot_sync(0xffffffffu, p);
        if (p) {
            int pos = cbase + __popc(m & lmask);
            if (pos < 32) {
                cu[warp][pos] = u[c];
                cj[warp][pos] = (c >> 2) * 128 + lane * 4 + (c & 3);
            }
        }
        cbase += __popc(m);
    }
    __syncwarp();

    if (cbase > 32) {
        // ---- rare exact fallback: successor-trick T, recompact ----
        unsigned base2 = 0;
        #pragma unroll 1
        for (int t = 0; t < KK; t++) {
            unsigned m2 = 0xFFFFFFFFu;
            #pragma unroll
            for (int c = 0; c < 32; c++) m2 = min(m2, u[c] - base2);
            #pragma unroll
            for (int off = 16; off; off >>= 1)
                m2 = min(m2, __shfl_xor_sync(0xffffffffu, m2, off));
            base2 += m2 + 1u;
        }
        unsigned Tt = base2 - 1u;
        int cb2 = 0;
        #pragma unroll
        for (int c = 0; c < 32; c++) {
            bool p = (u[c] <= Tt);
            unsigned m = __ballot_sync(0xffffffffu, p);
            if (p) {
                int pos = cb2 + __popc(m & lmask);
                if (pos < 32) {
                    cu[warp][pos] = u[c];
                    cj[warp][pos] = (c >> 2) * 128 + lane * 4 + (c & 3);
                }
            }
            cb2 += __popc(m);
        }
        cbase = cb2;
        __syncwarp();
    }

    // ---- pair bitonic sort (u asc, tie: j asc) across lanes ----
    unsigned su = (lane < cbase) ? cu[warp][lane] : 0xFFFFFFFFu;
    int      sj = (lane < cbase) ? cj[warp][lane] : 0x7FFFFFFF;
    #pragma unroll
    for (int k = 2; k <= 32; k <<= 1) {
        #pragma unroll
        for (int j2 = k >> 1; j2; j2 >>= 1) {
            unsigned ou = __shfl_xor_sync(0xffffffffu, su, j2);
            int      oj = __shfl_xor_sync(0xffffffffu, sj, j2);
            bool keepmin = (((lane & j2) == 0) != ((lane & k) != 0));
            bool oless = (ou < su) || (ou == su && oj < sj);
            if (keepmin == oless) { su = ou; sj = oj; }
        }
    }
    if (lane < KK) {
        sel_j[warp][lane] = sj;
        sel_d[warp][lane] = __uint_as_float(su);
    }
    __syncwarp();

    // ---- gather + weighted mean/max (ascending-distance order) ----
    float m0 = 0.f, m1 = 0.f, x0 = -3.4e38f, x1 = -3.4e38f;
    #pragma unroll 4
    for (int t = 0; t < KK; t++) {
        int   j  = sel_j[warp][t];
        float wt = __expf(-10.f * sel_d[warp][t]);
        const float* hp = g_h + (size_t)(gbase + j) * FLR;
        float v0 = hp[lane]      * wt;
        float v1 = hp[lane + 32] * wt;
        m0 += v0; m1 += v1;
        x0 = fmaxf(x0, v0); x1 = fmaxf(x1, v1);
    }
    float* ap = g_agg + (size_t)(gbase + li) * (2 * FLR);
    ap[lane]      = m0 * (1.f / 16.f);
    ap[lane + 32] = m1 * (1.f / 16.f);
    ap[64 + lane] = x0;
    ap[96 + lane] = x1;
}

// ---------------------------------------------------------------------------
// Kernel 3: HMMA bf16x3 GEMM, 512 threads / 16 warps (4x4 warp grid,
// 32x32 per warp) to double latency-hiding. Same proven addressing.
// ---------------------------------------------------------------------------
#define K3_AROW 272
#define K3_BROW 528
#define A_HI    0
#define A_LO    34816
#define B_HI    69632
#define B_LO    137216
#define K3_SMEM 204800

__global__ __launch_bounds__(512, 1) void k3_mma(
    const float* __restrict__ x,
    const float* __restrict__ bout,
    float* __restrict__ out)
{
    extern __shared__ __align__(16) char smem[];
    uint32_t sb = s2u(smem);
    int tid = threadIdx.x, warp = tid >> 5, lane = tid & 31;
    int wm = warp >> 2, wn = warp & 3;

    #pragma unroll
    for (int i = tid; i < 4096; i += 512) {
        uint4 vh = ((const uint4*)g_Wbhi)[i];
        uint4 vl = ((const uint4*)g_Wblo)[i];
        int n = i >> 5, c = i & 31;
        uint32_t off = (uint32_t)n * K3_BROW + (uint32_t)c * 16;
        sts128(sb + B_HI + off, vh.x, vh.y, vh.z, vh.w);
        sts128(sb + B_LO + off, vl.x, vl.y, vl.z, vl.w);
    }

    float2 bias[4];
    #pragma unroll
    for (int f = 0; f < 4; f++)
        bias[f] = *(const float2*)(bout + wn * 32 + f * 8 + (lane & 3) * 2);

    uint32_t aoff[2];
    #pragma unroll
    for (int mi = 0; mi < 2; mi++)
        aoff[mi] = (uint32_t)(wm * 32 + mi * 16 + (lane & 15)) * K3_AROW
                 + (uint32_t)((lane >> 4) * 16);
    uint32_t boff = (uint32_t)(wn * 32 + (lane & 7) + ((lane >> 4) << 3)) * K3_BROW
                  + (uint32_t)(((lane >> 3) & 1) * 16);

    for (int t = blockIdx.x; t < NN / 128; t += gridDim.x) {
        int r0 = t * 128;
        float c[2][4][4];
        #pragma unroll
        for (int mi = 0; mi < 2; mi++)
            #pragma unroll
            for (int f = 0; f < 4; f++)
                #pragma unroll
                for (int q = 0; q < 4; q++) c[mi][f][q] = 0.f;

        #pragma unroll
        for (int kc = 0; kc < 2; kc++) {
            __syncthreads();
            const float* src = kc ? g_agg : x;
            #pragma unroll
            for (int i = tid; i < 2048; i += 512) {
                int row = i >> 4, kk = (i & 15) * 8;
                const float* gp = src + (size_t)(r0 + row) * 128 + kk;
                float4 v0 = ((const float4*)gp)[0];
                float4 v1 = ((const float4*)gp)[1];
                uint32_t h0 = pk_hi(v0.x, v0.y), h1 = pk_hi(v0.z, v0.w);
                uint32_t h2 = pk_hi(v1.x, v1.y), h3 = pk_hi(v1.z, v1.w);
                uint32_t off = (uint32_t)row * K3_AROW + (uint32_t)kk * 2;
                sts128(sb + A_HI + off, h0, h1, h2, h3);
                sts128(sb + A_LO + off,
                       pk_lo_from(h0, v0.x, v0.y), pk_lo_from(h1, v0.z, v0.w),
                       pk_lo_from(h2, v1.x, v1.y), pk_lo_from(h3, v1.z, v1.w));
            }
            __syncthreads();

            #pragma unroll
            for (int ks = 0; ks < 8; ks++) {
                uint32_t ak = (uint32_t)ks * 32;
                uint32_t bk = (uint32_t)(kc * 8 + ks) * 32;
                uint32_t ah[2][4], al[2][4], bhf[2][4], blf[2][4];
                ldsm4(ah[0], sb + A_HI + aoff[0] + ak);
                ldsm4(ah[1], sb + A_HI + aoff[1] + ak);
                ldsm4(al[0], sb + A_LO + aoff[0] + ak);
                ldsm4(al[1], sb + A_LO + aoff[1] + ak);
                #pragma unroll
                for (int j2 = 0; j2 < 2; j2++) {
                    uint32_t ro = boff + (uint32_t)j2 * (16 * K3_BROW) + bk;
                    ldsm4(bhf[j2], sb + B_HI + ro);
                    ldsm4(blf[j2], sb + B_LO + ro);
                }
                #pragma unroll
                for (int mi = 0; mi < 2; mi++)
                    #pragma unroll
                    for (int f = 0; f < 4; f++) {
                        uint32_t b0 = bhf[f >> 1][(f & 1) * 2], b1 = bhf[f >> 1][(f & 1) * 2 + 1];
                        uint32_t l0 = blf[f >> 1][(f & 1) * 2], l1 = blf[f >> 1][(f & 1) * 2 + 1];
                        mma16816(c[mi][f], ah[mi], b0, b1);
                        mma16816(c[mi][f], ah[mi], l0, l1);
                        mma16816(c[mi][f], al[mi], b0, b1);
                    }
            }
        }

        #pragma unroll
        for (int mi = 0; mi < 2; mi++) {
            int row = r0 + wm * 32 + mi * 16 + (lane >> 2);
            #pragma unroll
            for (int f = 0; f < 4; f++) {
                int col = wn * 32 + f * 8 + (lane & 3) * 2;
                float2 v0, v1;
                v0.x = fmaxf(c[mi][f][0] + bias[f].x, 0.f);
                v0.y = fmaxf(c[mi][f][1] + bias[f].y, 0.f);
                v1.x = fmaxf(c[mi][f][2] + bias[f].x, 0.f);
                v1.y = fmaxf(c[mi][f][3] + bias[f].y, 0.f);
                *(float2*)(out + (size_t)row * OUTF + col)       = v0;
                *(float2*)(out + (size_t)(row + 8) * OUTF + col) = v1;
            }
        }
    }
}

// ---------------------------------------------------------------------------
extern "C" void kernel_launch(void* const* d_in, const int* in_sizes, int n_in,
                              void* d_out, int out_size)
{
    const float* x     = (const float*)d_in[0];
    const float* W_s   = (const float*)d_in[1];
    const float* b_s   = (const float*)d_in[2];
    const float* W_h   = (const float*)d_in[3];
    const float* b_h   = (const float*)d_in[4];
    const float* W_out = (const float*)d_in[5];
    const float* b_out = (const float*)d_in[6];
    // d_in[7] = batch (int64) — equal-size sorted graphs; unused.
    float* out = (float*)d_out;

    cudaFuncSetAttribute(k1h,    cudaFuncAttributeMaxDynamicSharedMemorySize, H_SMEM);
    cudaFuncSetAttribute(k3_mma, cudaFuncAttributeMaxDynamicSharedMemorySize, K3_SMEM);

    k0_convW<<<80, 256>>>(W_out, W_h);
    k1s<<<NN / 32, 256>>>(x, W_s, b_s);
    k1h<<<NN / 128, 256, H_SMEM>>>(x, b_h);
    k2_knn_agg<<<NB * (LG / 8), 256>>>();
    k3_mma<<<148, 512, K3_SMEM>>>(x, b_out, out);
}